// round 1
// baseline (speedup 1.0000x reference)
#include <cuda_runtime.h>

// Lattice LRU recurrence, fp32 baseline.
// Single persistent kernel, grid = 128 CTAs (all co-resident), custom
// wrap-safe grid barrier. Per cell: stage1 = big gate GEMM (128x2048,K=1024),
// stage2 = two candidate GEMMs (each 128x512,K=1024) + state update.
// Stage-1 epilogue also precomputes the elementwise products h1*r / h0*q so
// every stage-2 A-operand is a plain strided load.

#define H_    512
#define B_    128
#define T_    512
#define L_    4
#define J_    2
#define K2H   1024
#define N4H   2048
#define NBLK  128
#define NTHR  256
#define KC    32
#define NCHUNK (K2H / KC)

// ---- device scratch (no allocation allowed) ----
__device__ __align__(128) float d_g[B_ * N4H];        // sigmoid gates (z0,z1,r,q)
__device__ __align__(128) float d_ar[B_ * H_];        // h1 * r
__device__ __align__(128) float d_aq[B_ * H_];        // h0 * q
__device__ __align__(128) float d_h0buf[2][B_ * H_];  // ping-pong h0
__device__ __align__(128) float d_h1buf[2][B_ * H_];  // ping-pong h1
__device__ __align__(128) float d_H1[L_ * B_ * H_];   // persistent per-layer state
__device__ unsigned int g_bar = 0;

__device__ __forceinline__ void grid_barrier() {
    __syncthreads();
    if (threadIdx.x == 0) {
        __threadfence();
        unsigned ticket = atomicAdd(&g_bar, 1u);
        // NBLK = 128 divides 2^32 -> wrap-safe phase arithmetic
        unsigned target = (ticket & ~(unsigned)(NBLK - 1)) + NBLK;
        while ((int)(*(volatile unsigned*)&g_bar - target) < 0) {
            __nanosleep(32);
        }
        __threadfence();
    }
    __syncthreads();
}

// Tiled GEMM: C[128 x (8*CT)] tile, K = 1024.
// A assembled from two strided sources: a0 for k in [0,512), a1 for [512,1024).
// Thread (rowg = tid>>3, colg = tid&7) computes rows rowg*4..+3, cols colg*CT..+CT-1.
template <int CT>
__device__ __forceinline__ void gemm_tile(
    const float* __restrict__ a0, int lda0,
    const float* __restrict__ a1, int lda1,
    const float* __restrict__ W, int ldw,
    float* acc,
    float (*As)[KC + 4], float (*Bs)[20])
{
    const int tid  = threadIdx.x;
    const int rowg = tid >> 3;
    const int colg = tid & 7;

#pragma unroll
    for (int i = 0; i < 4 * CT; ++i) acc[i] = 0.f;

    const int  nb_f4 = 2 * CT;                 // float4s per k-row of B tile
    const bool bload = (tid < KC * nb_f4);
    const int  bk    = bload ? tid / nb_f4 : 0;
    const int  bc4   = bload ? tid % nb_f4 : 0;

    float4 av[4];
    float4 bv = make_float4(0.f, 0.f, 0.f, 0.f);

    // prologue: stage chunk 0 into registers
    {
#pragma unroll
        for (int i = 0; i < 4; ++i) {
            int idx = tid + i * NTHR;          // 0..1023
            int b = idx >> 3, f4 = idx & 7;
            av[i] = __ldcg((const float4*)(a0 + (size_t)b * lda0 + f4 * 4));
        }
        if (bload) bv = *(const float4*)(W + (size_t)bk * ldw + bc4 * 4);
    }

    for (int kc = 0; kc < NCHUNK; ++kc) {
        __syncthreads();                       // previous compute finished
#pragma unroll
        for (int i = 0; i < 4; ++i) {
            int idx = tid + i * NTHR;
            int b = idx >> 3, f4 = idx & 7;
            *(float4*)&As[b][f4 * 4] = av[i];
        }
        if (bload) *(float4*)&Bs[bk][bc4 * 4] = bv;
        __syncthreads();

        // prefetch next chunk (overlaps with compute below)
        if (kc + 1 < NCHUNK) {
            int kbase = (kc + 1) * KC;
            const float* asrc = (kbase < H_) ? a0 : a1;
            int lda  = (kbase < H_) ? lda0 : lda1;
            int koff = (kbase < H_) ? kbase : kbase - H_;
#pragma unroll
            for (int i = 0; i < 4; ++i) {
                int idx = tid + i * NTHR;
                int b = idx >> 3, f4 = idx & 7;
                av[i] = __ldcg((const float4*)(asrc + (size_t)b * lda + koff + f4 * 4));
            }
            if (bload) bv = *(const float4*)(W + (size_t)(kbase + bk) * ldw + bc4 * 4);
        }

#pragma unroll
        for (int kk = 0; kk < KC; ++kk) {
            float a0v = As[rowg * 4 + 0][kk];
            float a1v = As[rowg * 4 + 1][kk];
            float a2v = As[rowg * 4 + 2][kk];
            float a3v = As[rowg * 4 + 3][kk];
#pragma unroll
            for (int c = 0; c < CT; ++c) {
                float bb = Bs[kk][colg * CT + c];
                acc[0 * CT + c] = fmaf(a0v, bb, acc[0 * CT + c]);
                acc[1 * CT + c] = fmaf(a1v, bb, acc[1 * CT + c]);
                acc[2 * CT + c] = fmaf(a2v, bb, acc[2 * CT + c]);
                acc[3 * CT + c] = fmaf(a3v, bb, acc[3 * CT + c]);
            }
        }
    }
}

__global__ void __launch_bounds__(NTHR, 1) lattice_kernel(
    const float* __restrict__ H0in,
    const float* __restrict__ lin_w, const float* __restrict__ lin_b,
    const float* __restrict__ g0w,  const float* __restrict__ g0b,
    const float* __restrict__ g1w,  const float* __restrict__ g1b,
    float* __restrict__ out)
{
    __shared__ float As[B_][KC + 4];   // [128][36]
    __shared__ float Bs[KC][20];

    const int tid  = threadIdx.x;
    const int blk  = blockIdx.x;
    const int rowg = tid >> 3;
    const int colg = tid & 7;

    // reset persistent state every launch (graph replays reuse globals)
    for (int i = tid + blk * NTHR; i < L_ * B_ * H_; i += NBLK * NTHR)
        d_H1[i] = 0.f;
    grid_barrier();

    float* out_h1 = out + (size_t)B_ * T_ * H_;

    for (int t = 0; t < T_; ++t) {
        int p = 0;
        for (int l = 0; l < L_; ++l) {
            for (int j = 0; j < J_; ++j) {
                const int  cell  = l * J_ + j;
                const bool first = (l == 0 && j == 0);
                const bool last  = (l == L_ - 1 && j == J_ - 1);

                const float* h0src = first ? (H0in + (size_t)t * H_) : d_h0buf[p];
                const int    lda0  = first ? (T_ * H_) : H_;
                const float* h1src = (j == 0) ? (d_H1 + (size_t)l * B_ * H_) : d_h1buf[p];
                float*       h0dst = last ? (out + (size_t)t * H_) : d_h0buf[p ^ 1];
                const int    ldh0d = last ? (T_ * H_) : H_;
                float*       h1dst = (j == J_ - 1) ? (d_H1 + (size_t)l * B_ * H_)
                                                   : d_h1buf[p ^ 1];

                // ---------- stage 1: G = sigmoid([h0,h1] @ lin_w + lin_b) ----------
                {
                    const float* W = lin_w + (size_t)cell * K2H * N4H + blk * 16;
                    float acc[8];
                    gemm_tile<2>(h0src, lda0, h1src, H_, W, N4H, acc, As, Bs);

                    const int    colbase = blk * 16;
                    const float* bptr = lin_b + (size_t)cell * N4H + colbase;
#pragma unroll
                    for (int r = 0; r < 4; ++r) {
                        int b = rowg * 4 + r;
#pragma unroll
                        for (int c = 0; c < 2; ++c) {
                            int col = colbase + colg * 2 + c;
                            float v = acc[r * 2 + c] + bptr[colg * 2 + c];
                            float s = 1.f / (1.f + expf(-v));
                            d_g[b * N4H + col] = s;
                            if (col >= 2 * H_ && col < 3 * H_) {        // r-gate
                                int cc = col - 2 * H_;
                                d_ar[b * H_ + cc] = s * __ldcg(&h1src[b * H_ + cc]);
                            } else if (col >= 3 * H_) {                 // q-gate
                                int cc = col - 3 * H_;
                                d_aq[b * H_ + cc] =
                                    s * __ldcg(&h0src[(size_t)b * lda0 + cc]);
                            }
                        }
                    }
                }
                grid_barrier();

                // ---------- stage 2: candidates + state update ----------
                {
                    const int cc0 = blk * 8;
                    float acc[4];
                    if (cc0 < H_) {
                        // h0_cap = tanh([h0, h1*r] @ g0w + g0b); h1' = z1*h0_cap+(1-z1)*h1
                        const float* W = g0w + (size_t)cell * K2H * H_ + cc0;
                        gemm_tile<1>(h0src, lda0, d_ar, H_, W, H_, acc, As, Bs);
                        const float* bptr = g0b + (size_t)cell * H_ + cc0;
                        const int n = cc0 + colg;
#pragma unroll
                        for (int r = 0; r < 4; ++r) {
                            int b = rowg * 4 + r;
                            float hc  = tanhf(acc[r] + bptr[colg]);
                            float z1  = __ldcg(&d_g[b * N4H + H_ + n]);
                            float h1o = __ldcg(&h1src[b * H_ + n]);
                            h1dst[b * H_ + n] = z1 * hc + (1.f - z1) * h1o;
                        }
                    } else {
                        // h1_cap = tanh([h1, h0*q] @ g1w + g1b); h0' = z0*h1_cap+(1-z0)*h0
                        const int n0 = cc0 - H_;
                        const float* W = g1w + (size_t)cell * K2H * H_ + n0;
                        gemm_tile<1>(h1src, H_, d_aq, H_, W, H_, acc, As, Bs);
                        const float* bptr = g1b + (size_t)cell * H_ + n0;
                        const int n = n0 + colg;
#pragma unroll
                        for (int r = 0; r < 4; ++r) {
                            int b = rowg * 4 + r;
                            float hc  = tanhf(acc[r] + bptr[colg]);
                            float z0  = __ldcg(&d_g[b * N4H + n]);
                            float h0o = __ldcg(&h0src[(size_t)b * lda0 + n]);
                            h0dst[(size_t)b * ldh0d + n] = z0 * hc + (1.f - z0) * h0o;
                        }
                    }
                }
                grid_barrier();
                p ^= 1;
            }
        }
    }

    // H1_final: out2[b, l, h] = d_H1[l, b, h]
    for (int i = tid + blk * NTHR; i < L_ * B_ * H_; i += NBLK * NTHR) {
        int h    = i & (H_ - 1);
        int rest = i >> 9;          // l*B + b
        int b    = rest & (B_ - 1);
        int l    = rest >> 7;
        out_h1[((size_t)b * L_ + l) * H_ + h] = __ldcg(&d_H1[i]);
    }
}

extern "C" void kernel_launch(void* const* d_in, const int* in_sizes, int n_in,
                              void* d_out, int out_size)
{
    const float* H0in  = (const float*)d_in[0];
    const float* lin_w = (const float*)d_in[1];
    const float* lin_b = (const float*)d_in[2];
    const float* g0w   = (const float*)d_in[3];
    const float* g0b   = (const float*)d_in[4];
    const float* g1w   = (const float*)d_in[5];
    const float* g1b   = (const float*)d_in[6];

    lattice_kernel<<<NBLK, NTHR>>>(H0in, lin_w, lin_b, g0w, g0b, g1w, g1b,
                                   (float*)d_out);
}